// round 9
// baseline (speedup 1.0000x reference)
#include <cuda_runtime.h>
#include <cstdint>

#define NU    100000
#define NI    50000
#define NN    150000            // NU + NI
#define D     64
#define NNZ_  8000000
#define HOPS  3

// Static device scratch (per harness rules: no allocations).
__device__ int  g_cnt[NN];        // per-row edge count
__device__ int  g_start[NN];      // CSR row start
__device__ int  g_cursor[NN];     // scatter cursor
__device__ int4 g_edges[NNZ_];    // {col, val*2 (bits), keepmask(3 bits), pad}

// ---------------------------------------------------------------------------
// Init: out[:, 0, :] = concat(user, item)  (4 x float4 per thread, MLP=8)
//       + zero the row-count histogram.
// ---------------------------------------------------------------------------
__global__ void init_kernel(const float* __restrict__ user,
                            const float* __restrict__ item,
                            float* __restrict__ out) {
    int t = blockIdx.x * blockDim.x + threadIdx.x;
    if (t < NN) g_cnt[t] = 0;
    const int total = NN * D / 16;          // 600,000 threads
    if (t >= total) return;
    const int base   = t * 4;               // float4 index, aligned to 4
    const int userF4 = NU * D / 4;
    float4 v[4];
    #pragma unroll
    for (int i = 0; i < 4; ++i) {
        int idx = base + i;
        v[i] = (idx < userF4) ? ((const float4*)user)[idx]
                              : ((const float4*)item)[idx - userF4];
    }
    const int node = base >> 4;             // 16 float4 per node
    const int f4   = base & 15;
    #pragma unroll
    for (int i = 0; i < 4; ++i)
        ((float4*)out)[(size_t)node * 64 + f4 + i] = v[i];
}

// ---------------------------------------------------------------------------
// Histogram: g_cnt[rows[e]]++  (coalesced read, REDG to L2-resident counters)
// ---------------------------------------------------------------------------
__global__ void hist_kernel(const int* __restrict__ rows) {
    int t = blockIdx.x * blockDim.x + threadIdx.x;
    int nt = gridDim.x * blockDim.x;
    for (int e = t; e < NNZ_; e += nt)
        atomicAdd(&g_cnt[__ldcs(rows + e)], 1);
}

// ---------------------------------------------------------------------------
// Exclusive scan of g_cnt -> g_start, g_cursor. One block, 1024 threads.
// ---------------------------------------------------------------------------
__global__ void scan_kernel() {
    const int T = 1024;
    const int C = (NN + T - 1) / T;         // 147 rows per thread
    int t = threadIdx.x;
    int s = 0;
    for (int i = 0; i < C; ++i) {
        int r = t * C + i;
        if (r < NN) s += g_cnt[r];
    }
    // block-wide inclusive scan of per-thread sums
    int lane = t & 31, w = t >> 5;
    int v = s;
    #pragma unroll
    for (int o = 1; o < 32; o <<= 1) {
        int n = __shfl_up_sync(0xFFFFFFFFu, v, o);
        if (lane >= o) v += n;
    }
    __shared__ int ws[32];
    if (lane == 31) ws[w] = v;
    __syncthreads();
    if (w == 0) {
        int x = ws[lane];
        #pragma unroll
        for (int o = 1; o < 32; o <<= 1) {
            int n = __shfl_up_sync(0xFFFFFFFFu, x, o);
            if (lane >= o) x += n;
        }
        ws[lane] = x;
    }
    __syncthreads();
    int run = v - s + (w > 0 ? ws[w - 1] : 0);   // exclusive prefix for this thread
    for (int i = 0; i < C; ++i) {
        int r = t * C + i;
        if (r < NN) {
            g_start[r]  = run;
            g_cursor[r] = run;
            run += g_cnt[r];
        }
    }
}

// ---------------------------------------------------------------------------
// Scatter edges into CSR order. Payload packs col, scaled val, and the
// 3-hop keep mask (erand[h][e] >= 0.5) so per-hop kernels read coalesced.
// ---------------------------------------------------------------------------
__global__ void scatter_kernel(const int*   __restrict__ rows,
                               const int*   __restrict__ cols,
                               const float* __restrict__ vals,
                               const float* __restrict__ erand) {
    int t = blockIdx.x * blockDim.x + threadIdx.x;
    int nt = gridDim.x * blockDim.x;
    for (int e = t; e < NNZ_; e += nt) {
        int   r  = __ldcs(rows + e);
        int   c  = __ldcs(cols + e);
        float v  = __ldcs(vals + e) * 2.0f;      // edge-dropout scale 1/(1-0.5)
        int m = (__ldcs(erand + e)             >= 0.5f ? 1 : 0)
              | (__ldcs(erand + NNZ_ + e)      >= 0.5f ? 2 : 0)
              | (__ldcs(erand + 2 * NNZ_ + e)  >= 0.5f ? 4 : 0);
        int pos = atomicAdd(&g_cursor[r], 1);
        g_edges[pos] = make_int4(c, __float_as_int(v), m, 0);
    }
}

// ---------------------------------------------------------------------------
// Fused CSR SpMM + message dropout.
// One warp per row: acc in registers (float2/lane over D=64), gathers from
// src = out[:, hop, :] (node stride 256 floats). Up to 4 kept edges per
// ballot extraction — 4 gathers batched before the FMAs (MLP=4/warp).
// Epilogue applies message dropout and writes out[:, hop+1, :] directly.
// No atomics, no accumulator buffer.
// ---------------------------------------------------------------------------
__global__ void spmm_fused_kernel(const float* __restrict__ src,
                                  const float* __restrict__ mrand,
                                  float* __restrict__ out,
                                  int hop) {
    const int gw   = (blockIdx.x * blockDim.x + threadIdx.x) >> 5;
    const int lane = threadIdx.x & 31;
    const int nw   = (gridDim.x * blockDim.x) >> 5;

    for (int r = gw; r < NN; r += nw) {
        const int s = g_start[r];
        const int n = g_cnt[r];
        float accx = 0.f, accy = 0.f;
        for (int b = 0; b < n; b += 32) {
            int i = b + lane;
            int4 ed = (i < n) ? __ldcs(&g_edges[s + i]) : make_int4(0, 0, 0, 0);
            bool keep = (i < n) && ((ed.z >> hop) & 1);
            unsigned bm = __ballot_sync(0xFFFFFFFFu, keep);
            while (bm) {
                int l0 = __ffs(bm) - 1;              bm &= bm - 1;
                int l1 = bm ? __ffs(bm) - 1 : -1;    bm &= bm - 1;
                int l2 = bm ? __ffs(bm) - 1 : -1;    bm &= bm - 1;
                int l3 = bm ? __ffs(bm) - 1 : -1;    bm &= bm - 1;
                int   c0 = __shfl_sync(0xFFFFFFFFu, ed.x, l0 & 31);
                float v0 = __int_as_float(__shfl_sync(0xFFFFFFFFu, ed.y, l0 & 31));
                int   c1 = __shfl_sync(0xFFFFFFFFu, ed.x, l1 & 31);
                float v1 = __int_as_float(__shfl_sync(0xFFFFFFFFu, ed.y, l1 & 31));
                int   c2 = __shfl_sync(0xFFFFFFFFu, ed.x, l2 & 31);
                float v2 = __int_as_float(__shfl_sync(0xFFFFFFFFu, ed.y, l2 & 31));
                int   c3 = __shfl_sync(0xFFFFFFFFu, ed.x, l3 & 31);
                float v3 = __int_as_float(__shfl_sync(0xFFFFFFFFu, ed.y, l3 & 31));
                float2 x0, x1, x2, x3;
                x0 = __ldg((const float2*)(src + (size_t)c0 * 256) + lane);
                if (l1 >= 0) x1 = __ldg((const float2*)(src + (size_t)c1 * 256) + lane);
                if (l2 >= 0) x2 = __ldg((const float2*)(src + (size_t)c2 * 256) + lane);
                if (l3 >= 0) x3 = __ldg((const float2*)(src + (size_t)c3 * 256) + lane);
                accx += v0 * x0.x; accy += v0 * x0.y;
                if (l1 >= 0) { accx += v1 * x1.x; accy += v1 * x1.y; }
                if (l2 >= 0) { accx += v2 * x2.x; accy += v2 * x2.y; }
                if (l3 >= 0) { accx += v3 * x3.x; accy += v3 * x3.y; }
            }
        }
        // fused message dropout + write next hop slice
        float2 m = __ldcs((const float2*)(mrand + (size_t)r * 64) + lane);
        const float sc = 1.0f / 0.9f;
        float2 o;
        o.x = (m.x >= 0.1f) ? accx * sc : 0.f;
        o.y = (m.y >= 0.1f) ? accy * sc : 0.f;
        *((float2*)(out + (size_t)r * 256 + (size_t)(hop + 1) * 64) + lane) = o;
    }
}

// ---------------------------------------------------------------------------
extern "C" void kernel_launch(void* const* d_in, const int* in_sizes, int n_in,
                              void* d_out, int out_size) {
    const float* user  = (const float*)d_in[0];
    const float* item  = (const float*)d_in[1];
    const int*   rows  = (const int*)  d_in[2];
    const int*   cols  = (const int*)  d_in[3];
    const float* vals  = (const float*)d_in[4];
    const float* erand = (const float*)d_in[5];
    const float* mrand = (const float*)d_in[6];
    float*       out   = (float*)d_out;

    const int totalT    = NN * D / 16;      // 600,000
    const int ewThreads = 256;
    const int ewBlocks  = (totalT + ewThreads - 1) / ewThreads;

    const int gsBlocks  = 148 * 32;         // grid-stride kernels
    const int gsThreads = 256;

    // Launch order: 0 init, 1 hist, 2 scan, 3 scatter, 4 spmm0, 5 spmm1, 6 spmm2
    // (ncu -s 5 -c 1 → profiles spmm_fused hop 1)
    init_kernel<<<ewBlocks, ewThreads>>>(user, item, out);
    hist_kernel<<<gsBlocks, gsThreads>>>(rows);
    scan_kernel<<<1, 1024>>>();
    scatter_kernel<<<gsBlocks, gsThreads>>>(rows, cols, vals, erand);
    for (int hop = 0; hop < HOPS; ++hop) {
        spmm_fused_kernel<<<gsBlocks, gsThreads>>>(out + (size_t)hop * 64,
                                                   mrand + (size_t)hop * NN * D,
                                                   out, hop);
    }
}